// round 8
// baseline (speedup 1.0000x reference)
#include <cuda_runtime.h>
#include <cuda_bf16.h>
#include <stdint.h>
#include <math.h>

#define T_TOK 8192
#define DIM 1024
#define NEXP 16
#define INTER 2048
#define NROWS (2*T_TOK)

#define TM 64
#define TN 128
#define TKC 16
#define KW 12          // up: words per smem row (8 data + 4 pad)
#define DKC 32         // down: k elems per chunk
#define DKW 20         // down: words per smem row (16 data + 4 pad)

// ---------------- device scratch ----------------
__device__ int   g_cnt[NEXP];
__device__ int   g_rows[NEXP][T_TOK];   // value = 2*token + slot
__device__ float g_wt[NEXP][T_TOK];
__device__ uint32_t g_Hh[(size_t)NROWS * (INTER/2)];   // packed bf16 hi pairs
__device__ uint32_t g_Hl[(size_t)NROWS * (INTER/2)];   // packed bf16 lo pairs

#define MMA16816(d, a, b0, b1) \
    asm volatile("mma.sync.aligned.m16n8k16.row.col.f32.bf16.bf16.f32 " \
        "{%0,%1,%2,%3}, {%4,%5,%6,%7}, {%8,%9}, {%0,%1,%2,%3};" \
        : "+f"((d)[0]), "+f"((d)[1]), "+f"((d)[2]), "+f"((d)[3]) \
        : "r"((a)[0]), "r"((a)[1]), "r"((a)[2]), "r"((a)[3]), "r"(b0), "r"(b1))

// split fp32 pair -> packed bf16 hi pair + residual lo pair (lo16 = v0)
__device__ __forceinline__ void f2bf_pair(float v0, float v1,
                                          uint32_t& hi, uint32_t& lo) {
    uint32_t h;
    asm("cvt.rn.bf16x2.f32 %0, %1, %2;" : "=r"(h) : "f"(v1), "f"(v0));
    float h0 = __uint_as_float(h << 16);
    float h1 = __uint_as_float(h & 0xffff0000u);
    uint32_t l;
    asm("cvt.rn.bf16x2.f32 %0, %1, %2;" : "=r"(l) : "f"(v1 - h1), "f"(v0 - h0));
    hi = h; lo = l;
}

// ---------------- kernel 0: reset counters + zero output ----------------
__global__ void zero_kernel(float* __restrict__ y) {
    int i = blockIdx.x * blockDim.x + threadIdx.x;
    if (i < NEXP) g_cnt[i] = 0;
    if (i < T_TOK * DIM / 4) {
        float4 z = make_float4(0.f, 0.f, 0.f, 0.f);
        reinterpret_cast<float4*>(y)[i] = z;
    }
}

// ---------------- kernel 1: gate (unchanged, passing) ----------------
__global__ void gate_kernel(const float* __restrict__ x,
                            const float* __restrict__ Wg,
                            const float* __restrict__ bg) {
    int t = blockIdx.x;
    int tid = threadIdx.x;
    int e = tid & 15;
    int c = tid >> 4;
    __shared__ float part[8][17];
    __shared__ float sc[16];

    const float* xr = x + (size_t)t * DIM;
    const float* wc = Wg + e;
    float s = 0.f;
    int d0 = c * 128;
#pragma unroll 4
    for (int d = 0; d < 128; d++)
        s = fmaf(xr[d0 + d], wc[(size_t)(d0 + d) * NEXP], s);
    part[c][e] = s;
    __syncthreads();

    if (tid < 16) {
        float v = bg[tid];
#pragma unroll
        for (int cc = 0; cc < 8; cc++) v += part[cc][tid];
        sc[tid] = v;
    }
    __syncthreads();

    if (tid == 0) {
        int i1 = 0; float v1 = sc[0];
#pragma unroll
        for (int j = 1; j < 16; j++) if (sc[j] > v1) { v1 = sc[j]; i1 = j; }
        int i2 = -1; float v2 = -3.0e38f;
#pragma unroll
        for (int j = 0; j < 16; j++) if (j != i1 && sc[j] > v2) { v2 = sc[j]; i2 = j; }
        float r  = expf(v2 - v1);
        float w1 = 1.f / (1.f + r);
        float w2 = r   / (1.f + r);
        int p1 = atomicAdd(&g_cnt[i1], 1);
        g_rows[i1][p1] = 2 * t;     g_wt[i1][p1] = w1;
        int p2 = atomicAdd(&g_cnt[i2], 1);
        g_rows[i2][p2] = 2 * t + 1; g_wt[i2][p2] = w2;
    }
}

// ---------------- kernel 2: up projection (R7 mainloop, packed-H epilogue) -----
// grid: (INTER/TN, T_TOK/TM, NEXP), 256 threads; warps 2(m) x 4(n), warp 32x32
__global__ __launch_bounds__(256, 2)
void up_kernel(const float* __restrict__ x,
               const float* __restrict__ W1, const float* __restrict__ b1,
               const float* __restrict__ W3, const float* __restrict__ b3) {
    int e = blockIdx.z;
    int cnt = g_cnt[e];
    int m0 = blockIdx.y * TM;
    if (m0 >= cnt) return;
    int n0 = blockIdx.x * TN;

    __shared__ __align__(16) uint32_t sAh[TM*KW],  sAl[TM*KW];     // [row][k]
    __shared__ __align__(16) uint32_t sB1h[TN*KW], sB1l[TN*KW];    // [n][k]
    __shared__ __align__(16) uint32_t sB3h[TN*KW], sB3l[TN*KW];
    __shared__ int sTokRow[TM];
    __shared__ int sOutRow[TM];

    int tid = threadIdx.x;
    int wid = tid >> 5;
    int lane = tid & 31;
    int grp = lane >> 2;
    int tig = lane & 3;
    int wm = (wid >> 2) * 32;
    int wn = (wid & 3) * 32;

    if (tid < TM) {
        int m = m0 + tid;
        if (m < cnt) { int r = g_rows[e][m]; sTokRow[tid] = r >> 1; sOutRow[tid] = r; }
        else         { sTokRow[tid] = -1;    sOutRow[tid] = -1; }
    }
    __syncthreads();

    const float* W1e = W1 + (size_t)e * DIM * INTER + n0;
    const float* W3e = W3 + (size_t)e * DIM * INTER + n0;

    int arow = tid >> 2, aq = tid & 3;
    int myTok = sTokRow[arow];
    const float* aptr = (myTok >= 0) ? (x + (size_t)myTok * DIM + aq * 4) : x;
    int bn = tid & 127;
    int bkg = (tid >> 7) * 8;

    float4 rA;
    float rB1[8], rB3[8];
    const float4 zf4 = make_float4(0.f, 0.f, 0.f, 0.f);

    auto fetch = [&](int k0) {
        rA = (myTok >= 0) ? *reinterpret_cast<const float4*>(aptr + k0) : zf4;
#pragma unroll
        for (int j = 0; j < 8; j++) {
            rB1[j] = W1e[(size_t)(k0 + bkg + j) * INTER + bn];
            rB3[j] = W3e[(size_t)(k0 + bkg + j) * INTER + bn];
        }
    };
    auto stage = [&]() {
        uint32_t h0, l0, h1, l1;
        f2bf_pair(rA.x, rA.y, h0, l0);
        f2bf_pair(rA.z, rA.w, h1, l1);
        int ab = arow * KW + aq * 2;
        *reinterpret_cast<uint2*>(&sAh[ab]) = make_uint2(h0, h1);
        *reinterpret_cast<uint2*>(&sAl[ab]) = make_uint2(l0, l1);
        int bb = bn * KW + (bkg >> 1);
        uint32_t bh[4], bl[4];
#pragma unroll
        for (int j = 0; j < 4; j++) f2bf_pair(rB1[2*j], rB1[2*j+1], bh[j], bl[j]);
        *reinterpret_cast<uint4*>(&sB1h[bb]) = make_uint4(bh[0], bh[1], bh[2], bh[3]);
        *reinterpret_cast<uint4*>(&sB1l[bb]) = make_uint4(bl[0], bl[1], bl[2], bl[3]);
#pragma unroll
        for (int j = 0; j < 4; j++) f2bf_pair(rB3[2*j], rB3[2*j+1], bh[j], bl[j]);
        *reinterpret_cast<uint4*>(&sB3h[bb]) = make_uint4(bh[0], bh[1], bh[2], bh[3]);
        *reinterpret_cast<uint4*>(&sB3l[bb]) = make_uint4(bl[0], bl[1], bl[2], bl[3]);
    };

    float acc1[2][4][4], acc3[2][4][4];
#pragma unroll
    for (int mt = 0; mt < 2; mt++)
#pragma unroll
        for (int nt = 0; nt < 4; nt++)
#pragma unroll
            for (int j = 0; j < 4; j++) { acc1[mt][nt][j] = 0.f; acc3[mt][nt][j] = 0.f; }

    const int NC = DIM / TKC;   // 64
    fetch(0);
    for (int c = 0; c < NC; c++) {
        stage();
        __syncthreads();
        if (c + 1 < NC) fetch((c + 1) * TKC);

        uint32_t ah[2][4], al[2][4];
#pragma unroll
        for (int mt = 0; mt < 2; mt++) {
            int r0 = (wm + mt * 16 + grp) * KW;
            int r1 = r0 + 8 * KW;
            ah[mt][0] = sAh[r0 + tig];     ah[mt][1] = sAh[r1 + tig];
            ah[mt][2] = sAh[r0 + tig + 4]; ah[mt][3] = sAh[r1 + tig + 4];
            al[mt][0] = sAl[r0 + tig];     al[mt][1] = sAl[r1 + tig];
            al[mt][2] = sAl[r0 + tig + 4]; al[mt][3] = sAl[r1 + tig + 4];
        }
#pragma unroll
        for (int nt = 0; nt < 4; nt++) {
            int nb = (wn + nt * 8 + grp) * KW;
            uint32_t b1h0 = sB1h[nb + tig], b1h1 = sB1h[nb + tig + 4];
            uint32_t b1l0 = sB1l[nb + tig], b1l1 = sB1l[nb + tig + 4];
            uint32_t b3h0 = sB3h[nb + tig], b3h1 = sB3h[nb + tig + 4];
            uint32_t b3l0 = sB3l[nb + tig], b3l1 = sB3l[nb + tig + 4];
#pragma unroll
            for (int mt = 0; mt < 2; mt++) {
                MMA16816(acc1[mt][nt], ah[mt], b1h0, b1h1);
                MMA16816(acc1[mt][nt], ah[mt], b1l0, b1l1);
                MMA16816(acc1[mt][nt], al[mt], b1h0, b1h1);
                MMA16816(acc3[mt][nt], ah[mt], b3h0, b3h1);
                MMA16816(acc3[mt][nt], ah[mt], b3l0, b3l1);
                MMA16816(acc3[mt][nt], al[mt], b3h0, b3h1);
            }
        }
        __syncthreads();
    }

    // epilogue: h = silu(z1+b1)*(z3+b3) -> packed split-bf16 H
    const float* pb1 = b1 + (size_t)e * INTER + n0;
    const float* pb3 = b3 + (size_t)e * INTER + n0;
#pragma unroll
    for (int mt = 0; mt < 2; mt++) {
#pragma unroll
        for (int half = 0; half < 2; half++) {
            int rloc = wm + mt * 16 + grp + half * 8;
            int hr = sOutRow[rloc];
            if (hr < 0) continue;
            uint32_t* pHh = g_Hh + (size_t)hr * (INTER/2) + n0/2;
            uint32_t* pHl = g_Hl + (size_t)hr * (INTER/2) + n0/2;
#pragma unroll
            for (int nt = 0; nt < 4; nt++) {
                int col = wn + nt * 8 + tig * 2;
                float z1a = acc1[mt][nt][half * 2]     + pb1[col];
                float z1b = acc1[mt][nt][half * 2 + 1] + pb1[col + 1];
                float z3a = acc3[mt][nt][half * 2]     + pb3[col];
                float z3b = acc3[mt][nt][half * 2 + 1] + pb3[col + 1];
                float ha = (z1a / (1.f + expf(-z1a))) * z3a;
                float hb = (z1b / (1.f + expf(-z1b))) * z3b;
                uint32_t hp, lp;
                f2bf_pair(ha, hb, hp, lp);
                pHh[col >> 1] = hp;
                pHl[col >> 1] = lp;
            }
        }
    }
}

// ---------------- kernel 3: down projection (TKC=32, packed-H A path) ----------
// grid: (DIM/TN, T_TOK/TM, NEXP), 256 threads; warps 2(m) x 4(n)
__global__ __launch_bounds__(256, 2)
void down_kernel(const float* __restrict__ W2, const float* __restrict__ b2,
                 float* __restrict__ y) {
    int e = blockIdx.z;
    int cnt = g_cnt[e];
    int m0 = blockIdx.y * TM;
    if (m0 >= cnt) return;
    int n0 = blockIdx.x * TN;

    __shared__ __align__(16) uint32_t sAh[TM*DKW], sAl[TM*DKW];   // [row][k] 16 data words
    __shared__ __align__(16) uint32_t sBh[TN*DKW], sBl[TN*DKW];
    __shared__ int   sHRow[TM];
    __shared__ int   sTok[TM];
    __shared__ float sW[TM];

    int tid = threadIdx.x;
    int wid = tid >> 5;
    int lane = tid & 31;
    int grp = lane >> 2;
    int tig = lane & 3;
    int wm = (wid >> 2) * 32;
    int wn = (wid & 3) * 32;

    if (tid < TM) {
        int m = m0 + tid;
        if (m < cnt) {
            int r = g_rows[e][m];
            sHRow[tid] = r; sTok[tid] = r >> 1; sW[tid] = g_wt[e][m];
        } else { sHRow[tid] = -1; sTok[tid] = -1; sW[tid] = 0.f; }
    }
    __syncthreads();

    const float* W2e = W2 + (size_t)e * INTER * DIM + n0;   // [k][n]

    // A loader: row = tid>>2 (0..63), aq = tid&3 -> 8 k-elems = 4 packed words
    int arow = tid >> 2, aq = tid & 3;
    int myH = sHRow[arow];
    const uint4* pAh = (const uint4*)(g_Hh + (size_t)(myH < 0 ? 0 : myH) * (INTER/2)) + aq;
    const uint4* pAl = (const uint4*)(g_Hl + (size_t)(myH < 0 ? 0 : myH) * (INTER/2)) + aq;
    // B loader: n = tid&127, kg = (tid>>7)*16 -> 16 k-elems (transpose in regs)
    int bn = tid & 127;
    int bkg = (tid >> 7) * 16;

    uint4 rAh, rAl;
    float rB[16];
    const uint4 zu4 = make_uint4(0, 0, 0, 0);

    auto fetch = [&](int k0) {
        // k0 in elems; pair offset k0/2; uint4 index k0/8
        rAh = (myH >= 0) ? pAh[k0 >> 3] : zu4;
        rAl = (myH >= 0) ? pAl[k0 >> 3] : zu4;
#pragma unroll
        for (int j = 0; j < 16; j++)
            rB[j] = W2e[(size_t)(k0 + bkg + j) * DIM + bn];
    };
    auto stage = [&]() {
        int ab = arow * DKW + aq * 4;
        *reinterpret_cast<uint4*>(&sAh[ab]) = rAh;
        *reinterpret_cast<uint4*>(&sAl[ab]) = rAl;
        int bb = bn * DKW + (bkg >> 1);
        uint32_t bh[8], bl[8];
#pragma unroll
        for (int j = 0; j < 8; j++) f2bf_pair(rB[2*j], rB[2*j+1], bh[j], bl[j]);
        *reinterpret_cast<uint4*>(&sBh[bb])     = make_uint4(bh[0], bh[1], bh[2], bh[3]);
        *reinterpret_cast<uint4*>(&sBh[bb + 4]) = make_uint4(bh[4], bh[5], bh[6], bh[7]);
        *reinterpret_cast<uint4*>(&sBl[bb])     = make_uint4(bl[0], bl[1], bl[2], bl[3]);
        *reinterpret_cast<uint4*>(&sBl[bb + 4]) = make_uint4(bl[4], bl[5], bl[6], bl[7]);
    };

    float acc[2][4][4];
#pragma unroll
    for (int mt = 0; mt < 2; mt++)
#pragma unroll
        for (int nt = 0; nt < 4; nt++)
#pragma unroll
            for (int j = 0; j < 4; j++) acc[mt][nt][j] = 0.f;

    const int NC = INTER / DKC;   // 64
    fetch(0);
    for (int c = 0; c < NC; c++) {
        stage();
        __syncthreads();
        if (c + 1 < NC) fetch((c + 1) * DKC);

#pragma unroll
        for (int ks = 0; ks < 2; ks++) {
            int ko = ks * 8;
            uint32_t ah[2][4], al[2][4];
#pragma unroll
            for (int mt = 0; mt < 2; mt++) {
                int r0 = (wm + mt * 16 + grp) * DKW + ko;
                int r1 = r0 + 8 * DKW;
                ah[mt][0] = sAh[r0 + tig];     ah[mt][1] = sAh[r1 + tig];
                ah[mt][2] = sAh[r0 + tig + 4]; ah[mt][3] = sAh[r1 + tig + 4];
                al[mt][0] = sAl[r0 + tig];     al[mt][1] = sAl[r1 + tig];
                al[mt][2] = sAl[r0 + tig + 4]; al[mt][3] = sAl[r1 + tig + 4];
            }
#pragma unroll
            for (int nt = 0; nt < 4; nt++) {
                int nb = (wn + nt * 8 + grp) * DKW + ko;
                uint32_t bh0 = sBh[nb + tig], bh1 = sBh[nb + tig + 4];
                uint32_t bl0 = sBl[nb + tig], bl1 = sBl[nb + tig + 4];
#pragma unroll
                for (int mt = 0; mt < 2; mt++) {
                    MMA16816(acc[mt][nt], ah[mt], bh0, bh1);
                    MMA16816(acc[mt][nt], ah[mt], bl0, bl1);
                    MMA16816(acc[mt][nt], al[mt], bh0, bh1);
                }
            }
        }
        __syncthreads();
    }

    // epilogue: weight + deterministic 2-addend scatter-add (unchanged)
    const float* pb2 = b2 + (size_t)e * DIM + n0;
#pragma unroll
    for (int mt = 0; mt < 2; mt++) {
#pragma unroll
        for (int half = 0; half < 2; half++) {
            int rloc = wm + mt * 16 + grp + half * 8;
            int tok = sTok[rloc];
            if (tok < 0) continue;
            float w = sW[rloc];
            float* yr = y + (size_t)tok * DIM + n0;
#pragma unroll
            for (int nt = 0; nt < 4; nt++) {
                int col = wn + nt * 8 + tig * 2;
                atomicAdd(yr + col,     (acc[mt][nt][half * 2]     + pb2[col])     * w);
                atomicAdd(yr + col + 1, (acc[mt][nt][half * 2 + 1] + pb2[col + 1]) * w);
            }
        }
    }
}

// -------------------------------- launcher --------------------------------------
extern "C" void kernel_launch(void* const* d_in, const int* in_sizes, int n_in,
                              void* d_out, int out_size) {
    const float* x  = (const float*)d_in[0];
    const float* Wg = (const float*)d_in[1];
    const float* bg = (const float*)d_in[2];
    const float* W1 = (const float*)d_in[3];
    const float* b1 = (const float*)d_in[4];
    const float* W2 = (const float*)d_in[5];
    const float* b2 = (const float*)d_in[6];
    const float* W3 = (const float*)d_in[7];
    const float* b3 = (const float*)d_in[8];
    float* y = (float*)d_out;

    zero_kernel<<<(T_TOK * DIM / 4 + 255) / 256, 256>>>(y);
    gate_kernel<<<T_TOK, 128>>>(x, Wg, bg);

    dim3 upGrid(INTER / TN, T_TOK / TM, NEXP);
    up_kernel<<<upGrid, 256>>>(x, W1, b1, W3, b3);

    dim3 dnGrid(DIM / TN, T_TOK / TM, NEXP);
    down_kernel<<<dnGrid, 256>>>(W2, b2, y);
}